// round 15
// baseline (speedup 1.0000x reference)
#include <cuda_runtime.h>

#define IMW 128
#define IMH 128
#define HW 16384
#define NPTS 16384
#define NCELLS 16384
#define KNN 16
#define FDIM 64
#define CAP 24          // bin capacity per cell (Poisson(1); P(>24) ~ 1e-24)
#define NOFF 21         // 5x5 window minus 4 corners (min d2 = 4.5 > 4)
#define MAXC 48         // max candidates kept (Poisson(12.6); P(>48) ~ 1e-13)

// float32 output packing: depths | colors(HW*3) | feats(HW*64) | masks
#define OFF_DEP  0
#define OFF_COL  16384
#define OFF_FEAT 65536
#define OFF_MASK 1114112

#define FULL 0xFFFFFFFFu

// ---- scratch (device globals; no cudaMalloc allowed) ----
__device__ int    g_cnt[NCELLS];
__device__ float4 g_bin[NCELLS * CAP];
__device__ float2 g_list[KNN * HW];   // SoA: slot k of pixel p at [k*HW + p]
__device__ float  g_wsum[HW];

// relative (dr,dc) offsets of the 21 reachable cells
__constant__ signed char c_off[NOFF][2] = {
            {-2,-1},{-2,0},{-2,1},
    {-1,-2},{-1,-1},{-1,0},{-1,1},{-1,2},
    { 0,-2},{ 0,-1},{ 0,0},{ 0,1},{ 0,2},
    { 1,-2},{ 1,-1},{ 1,0},{ 1,1},{ 1,2},
            { 2,-1},{ 2,0},{ 2,1}
};

__global__ void k_bin(const float* __restrict__ pts, const float* __restrict__ intr) {
    int i = blockIdx.x * blockDim.x + threadIdx.x;
    if (i >= NPTS) return;
    float x = pts[3 * i + 0];
    float y = pts[3 * i + 1];
    float z = pts[3 * i + 2];
    if (z <= 1e-6f) return;                    // FAR point: never within radius
    float u = x * intr[0] / z + intr[2];       // same op order as reference
    float v = y * intr[4] / z + intr[5];
    int cu = min(max((int)floorf(u), 0), IMW - 1);
    int cv = min(max((int)floorf(v), 0), IMH - 1);
    int c = cv * IMW + cu;
    int pos = atomicAdd(&g_cnt[c], 1);
    if (pos < CAP) g_bin[c * CAP + pos] = make_float4(u, v, z, __int_as_float(i));
}

// THREAD per pixel: serial scan of own 21-cell window (L1-hot: block's pixels
// share a 6-row cell band). Writes (wk,id) list + wsum + depth + mask.
// Pixels with >16 in-radius handled warp-cooperatively afterwards.
__global__ void __launch_bounds__(128)
k_select(float* __restrict__ out) {
    __shared__ float  s_d2[4][MAXC];
    __shared__ float  s_z [4][MAXC];
    __shared__ float2 s_wi[4][MAXC];

    int p = blockIdx.x * 128 + threadIdx.x;
    int lane = threadIdx.x & 31;
    int wq = threadIdx.x >> 5;
    unsigned lt = (1u << lane) - 1u;

    int pi = p >> 7, pj = p & 127;
    float uc = (float)pj + 0.5f;
    float vc = (float)pi + 0.5f;

    // prefetch all 21 cell counts/bases (independent loads -> one latency wave)
    int cc[NOFF], bb[NOFF];
#pragma unroll
    for (int o = 0; o < NOFF; o++) {
        int r = pi + c_off[o][0];
        int c = pj + c_off[o][1];
        cc[o] = 0; bb[o] = 0;
        if ((unsigned)r < IMH && (unsigned)c < IMW) {
            int cell = r * IMW + c;
            cc[o] = min(g_cnt[cell], CAP);
            bb[o] = cell * CAP;
        }
    }

    int n = 0;
    float wsum = 0.0f, dep = 0.0f;
#pragma unroll
    for (int o = 0; o < NOFF; o++) {
        for (int j = 0; j < cc[o]; j++) {
            float4 pt = g_bin[bb[o] + j];
            float du = pt.x - uc;
            float dv = pt.y - vc;
            float d2 = du * du + dv * dv;
            if (d2 < 4.0f) {
                if (n < KNN) {
                    float wk = __expf(-d2);
                    wsum += wk;
                    dep  += wk * pt.z;
                    g_list[n * HW + p] = make_float2(wk, pt.w);
                }
                n++;
            }
        }
    }

    if (n <= KNN) {
        for (int k = n; k < KNN; k++)
            g_list[k * HW + p] = make_float2(0.0f, 0.0f);   // id 0, wk 0 pad
        float inv = 1.0f / (wsum + 1e-10f);
        out[OFF_DEP + p]  = dep * inv;
        out[OFF_MASK + p] = (n > 0) ? 1.0f : 0.0f;
        g_wsum[p] = wsum;
    }

    // ---- warp-cooperative pass over this warp's slow pixels (>16) ----
    unsigned smask = __ballot_sync(FULL, n > KNN);
    while (smask) {
        int t = __ffs(smask) - 1;
        smask &= smask - 1;
        int sp = (p - lane) + t;               // warp covers 32 consecutive pixels
        int spi = sp >> 7, spj = sp & 127;
        float suc = (float)spj + 0.5f;
        float svc = (float)spi + 0.5f;

        int cnt_l = 0, base_l = 0;
        if (lane < NOFF) {
            int r = spi + c_off[lane][0];
            int c = spj + c_off[lane][1];
            if ((unsigned)r < IMH && (unsigned)c < IMW) {
                int cell = r * IMW + c;
                cnt_l = min(g_cnt[cell], CAP);
                base_l = cell * CAP;
            }
        }
        int maxc = cnt_l;
#pragma unroll
        for (int off = 16; off >= 1; off >>= 1)
            maxc = max(maxc, __shfl_xor_sync(FULL, maxc, off));

        int nval = 0;
#pragma unroll 1
        for (int j = 0; j < maxc; j++) {
            bool valid = false;
            float d2 = 0.0f, wk = 0.0f, z = 0.0f, idb = 0.0f;
            if (j < cnt_l) {
                float4 pt = g_bin[base_l + j];
                float du = pt.x - suc;
                float dv = pt.y - svc;
                d2 = du * du + dv * dv;
                if (d2 < 4.0f) {
                    valid = true;
                    wk = __expf(-d2);
                    z = pt.z;
                    idb = pt.w;
                }
            }
            unsigned bal = __ballot_sync(FULL, valid);
            int rk = nval + __popc(bal & lt);
            if (valid && rk < MAXC) {
                s_d2[wq][rk] = d2;
                s_z [wq][rk] = z;
                s_wi[wq][rk] = make_float2(wk, idb);
            }
            nval += __popc(bal);
        }
        nval = min(nval, MAXC);
        __syncwarp();

        // parallel rank selection of 16 smallest d2
        bool own0 = lane < nval;
        bool own1 = lane + 32 < nval;
        float d20 = own0 ? s_d2[wq][lane] : 0.0f;
        float d21 = own1 ? s_d2[wq][lane + 32] : 0.0f;
        float2 wi0 = own0 ? s_wi[wq][lane] : make_float2(0.0f, 0.0f);
        float2 wi1 = own1 ? s_wi[wq][lane + 32] : make_float2(0.0f, 0.0f);
        float z0 = own0 ? s_z[wq][lane] : 0.0f;
        float z1 = own1 ? s_z[wq][lane + 32] : 0.0f;

        int r0 = 0, r1 = 0;
#pragma unroll 4
        for (int j = 0; j < nval; j++) {
            float dj = s_d2[wq][j];
            r0 += (dj < d20) || (dj == d20 && j < lane);
            r1 += (dj < d21) || (dj == d21 && j < lane + 32);
        }
        bool sel0 = own0 && r0 < KNN;
        bool sel1 = own1 && r1 < KNN;

        float ls = 0.0f, ld = 0.0f;
        if (sel0) { ls += wi0.x; ld += wi0.x * z0; }
        if (sel1) { ls += wi1.x; ld += wi1.x * z1; }
#pragma unroll
        for (int off = 16; off >= 1; off >>= 1) {
            ls += __shfl_xor_sync(FULL, ls, off);
            ld += __shfl_xor_sync(FULL, ld, off);
        }

        unsigned b0 = __ballot_sync(FULL, sel0);
        unsigned b1 = __ballot_sync(FULL, sel1);
        if (sel0) g_list[(__popc(b0 & lt)) * HW + sp] = wi0;
        if (sel1) g_list[(__popc(b0) + __popc(b1 & lt)) * HW + sp] = wi1;
        if (lane == 0) {
            float inv = 1.0f / (ls + 1e-10f);
            out[OFF_DEP + sp]  = ld * inv;
            out[OFF_MASK + sp] = 1.0f;
            g_wsum[sp] = ls;
        }
        __syncwarp();
    }
}

// WARP per pixel: streaming accumulation of colors + 64-dim feats.
__global__ void __launch_bounds__(256)
k_accum(const float* __restrict__ colors, const float* __restrict__ feats,
        float* __restrict__ out) {
    int gt = blockIdx.x * blockDim.x + threadIdx.x;
    int p = gt >> 5;
    int lane = gt & 31;
    if (p >= HW) return;
    int half = lane >> 4;
    int hl   = lane & 15;

    float4 acc = make_float4(0.0f, 0.0f, 0.0f, 0.0f);
    float col = 0.0f;
#pragma unroll
    for (int t = 0; t < KNN / 2; t++) {
        int k = 2 * t + half;
        float2 wi = g_list[k * HW + p];     // broadcast (2 addrs per warp, L2-hot)
        float wk = wi.x;
        int   id = __float_as_int(wi.y);
        const float4* row = (const float4*)(feats + (long)id * FDIM);
        float4 f = row[hl];                 // 16 lanes x 16B = 256B row
        acc.x += wk * f.x;
        acc.y += wk * f.y;
        acc.z += wk * f.z;
        acc.w += wk * f.w;
        if (hl < 3) col += wk * colors[3 * id + hl];
    }
    acc.x += __shfl_xor_sync(FULL, acc.x, 16);
    acc.y += __shfl_xor_sync(FULL, acc.y, 16);
    acc.z += __shfl_xor_sync(FULL, acc.z, 16);
    acc.w += __shfl_xor_sync(FULL, acc.w, 16);
    col   += __shfl_xor_sync(FULL, col, 16);

    float inv = 1.0f / (g_wsum[p] + 1e-10f);
    if (lane < 3) out[OFF_COL + 3 * p + lane] = col * inv;
    if (half == 0) {
        float4 o = make_float4(acc.x * inv, acc.y * inv, acc.z * inv, acc.w * inv);
        ((float4*)(out + OFF_FEAT + p * FDIM))[hl] = o;
    }
}

extern "C" void kernel_launch(void* const* d_in, const int* in_sizes, int n_in,
                              void* d_out, int out_size) {
    const float* pts    = (const float*)d_in[0];   // (N,3)
    const float* colors = (const float*)d_in[1];   // (N,3)
    const float* feats  = (const float*)d_in[2];   // (N,64)
    const float* intr   = (const float*)d_in[3];   // (3,3)
    float* out = (float*)d_out;

    void* cnt_addr = nullptr;
    cudaGetSymbolAddress(&cnt_addr, g_cnt);
    cudaMemsetAsync(cnt_addr, 0, NCELLS * sizeof(int), 0);

    k_bin   <<<NPTS / 128, 128>>>(pts, intr);
    k_select<<<HW / 128, 128>>>(out);
    k_accum <<<(HW * 32) / 256, 256>>>(colors, feats, out);
}